// round 1
// baseline (speedup 1.0000x reference)
#include <cuda_runtime.h>
#include <cstdint>

#define DIM    1024
#define QKV_N  3072
#define MTOT   4096          // B*N
#define SEQ    2048
#define RANK   8
#define LSCALE 2.0f          // lora scaling 16/8
#define QSCALE 0.125f        // 64^-0.5

// -------- scratch (static device globals: allocation-free) --------
__device__ float g_qkv[MTOT * QKV_N];   // [B,N,3C]
__device__ float g_attn[MTOT * DIM];    // [B,N,C]
__device__ float g_t1[MTOT * RANK];
__device__ float g_t2[MTOT * RANK];

// ---------------- LoRA down-projection: t = LSCALE * (X @ A^T) ----------------
// one warp per row of X
__global__ void lora_down_kernel(const float* __restrict__ x,
                                 const float* __restrict__ A,
                                 float* __restrict__ t)
{
    int warp = (blockIdx.x * blockDim.x + threadIdx.x) >> 5;
    int lane = threadIdx.x & 31;
    if (warp >= MTOT) return;
    const float* xr = x + (size_t)warp * DIM;
    float acc[RANK];
#pragma unroll
    for (int r = 0; r < RANK; r++) acc[r] = 0.f;
    for (int k = lane; k < DIM; k += 32) {
        float xv = xr[k];
#pragma unroll
        for (int r = 0; r < RANK; r++) acc[r] += xv * A[r * DIM + k];
    }
#pragma unroll
    for (int r = 0; r < RANK; r++) {
#pragma unroll
        for (int off = 16; off > 0; off >>= 1)
            acc[r] += __shfl_xor_sync(0xffffffffu, acc[r], off);
    }
    if (lane == 0) {
#pragma unroll
        for (int r = 0; r < RANK; r++)
            t[warp * RANK + r] = LSCALE * acc[r];
    }
}

// ---------------- SGEMM: C = A[M,K] @ W[N,K]^T  (+ epilogues) ----------------
// EPI==1: qkv  -> C += lt @ lB^T ; q columns (gc < DIM) scaled by QSCALE
// EPI==2: proj -> C += lt @ lB^T + bias
// 128x128 tile, BK=16, 256 threads, 8x8 per thread
template<int EPI>
__global__ void __launch_bounds__(256, 2) sgemm_epi(
    const float* __restrict__ A, const float* __restrict__ W,
    float* __restrict__ C, int M, int N, int K,
    const float* __restrict__ lt, const float* __restrict__ lB,
    const float* __restrict__ bias)
{
    __shared__ float As[16][128];
    __shared__ float Bs[16][128];
    const int tid = threadIdx.x;
    const int bm = blockIdx.y * 128, bn = blockIdx.x * 128;
    const int lr = tid >> 2;              // 0..63
    const int lc = (tid & 3) << 2;        // 0,4,8,12
    const int ty = tid >> 4, tx = tid & 15;

    float acc[8][8];
#pragma unroll
    for (int i = 0; i < 8; i++)
#pragma unroll
        for (int j = 0; j < 8; j++) acc[i][j] = 0.f;

    const float* Ap0 = A + (size_t)(bm + lr) * K + lc;
    const float* Ap1 = A + (size_t)(bm + lr + 64) * K + lc;
    const float* Wp0 = W + (size_t)(bn + lr) * K + lc;
    const float* Wp1 = W + (size_t)(bn + lr + 64) * K + lc;

    for (int k0 = 0; k0 < K; k0 += 16) {
        float4 a0 = *(const float4*)(Ap0 + k0);
        float4 a1 = *(const float4*)(Ap1 + k0);
        float4 b0 = *(const float4*)(Wp0 + k0);
        float4 b1 = *(const float4*)(Wp1 + k0);
        __syncthreads();
        As[lc + 0][lr] = a0.x; As[lc + 1][lr] = a0.y;
        As[lc + 2][lr] = a0.z; As[lc + 3][lr] = a0.w;
        As[lc + 0][lr + 64] = a1.x; As[lc + 1][lr + 64] = a1.y;
        As[lc + 2][lr + 64] = a1.z; As[lc + 3][lr + 64] = a1.w;
        Bs[lc + 0][lr] = b0.x; Bs[lc + 1][lr] = b0.y;
        Bs[lc + 2][lr] = b0.z; Bs[lc + 3][lr] = b0.w;
        Bs[lc + 0][lr + 64] = b1.x; Bs[lc + 1][lr + 64] = b1.y;
        Bs[lc + 2][lr + 64] = b1.z; Bs[lc + 3][lr + 64] = b1.w;
        __syncthreads();
#pragma unroll
        for (int kk = 0; kk < 16; kk++) {
            float a[8], b[8];
            *(float4*)&a[0] = *(const float4*)&As[kk][ty * 8];
            *(float4*)&a[4] = *(const float4*)&As[kk][ty * 8 + 4];
            *(float4*)&b[0] = *(const float4*)&Bs[kk][tx * 8];
            *(float4*)&b[4] = *(const float4*)&Bs[kk][tx * 8 + 4];
#pragma unroll
            for (int i = 0; i < 8; i++)
#pragma unroll
                for (int j = 0; j < 8; j++)
                    acc[i][j] += a[i] * b[j];
        }
    }

    const int row0 = bm + ty * 8, col0 = bn + tx * 8;
#pragma unroll
    for (int j = 0; j < 8; j++) {
        const int gc = col0 + j;
        float bj[RANK];
#pragma unroll
        for (int r = 0; r < RANK; r++) bj[r] = lB[gc * RANK + r];
        const float bb = (EPI == 2) ? bias[gc] : 0.f;
#pragma unroll
        for (int i = 0; i < 8; i++) {
            const int gr = row0 + i;
            const float* tv = lt + gr * RANK;
            float s = acc[i][j];
#pragma unroll
            for (int r = 0; r < RANK; r++) s += tv[r] * bj[r];
            s += bb;
            if (EPI == 1 && gc < DIM) s *= QSCALE;
            C[(size_t)gr * N + gc] = s;
        }
    }
}

// ---------------- Flash attention, fp32, 64x64 tiles ----------------
// grid (32 qtiles, 16 heads, 2 batch), 256 threads (16x16), 4x4 per thread.
// q pre-scaled by QSCALE in the qkv epilogue.
#define PADT 68   // padded stride (floats) for transposed tiles; 68*4B % 16 == 0

__global__ void __launch_bounds__(256) attn_kernel(const float* __restrict__ qkv,
                                                   float* __restrict__ aout)
{
    extern __shared__ float sm[];
    float* qT = sm;                 // [d][i] stride PADT   (64*68)
    float* kT = sm + 64 * PADT;     // [d][j] stride PADT
    float* pT = sm + 2 * 64 * PADT; // [j][i] stride PADT
    float* vS = sm + 3 * 64 * PADT; // [j][c] stride 64     (64*64)

    const int tid = threadIdx.x;
    const int ty = tid >> 4, tx = tid & 15;
    const int i0 = ty << 2, c0 = tx << 2;   // c0 doubles as j0 for S
    const int qt = blockIdx.x, h = blockIdx.y, b = blockIdx.z;
    const float* base = qkv + (size_t)b * SEQ * QKV_N;
    const int qrow0 = qt * 64;
    const int hoff = h * 64;

    // load Q tile (transposed: d-major)
#pragma unroll
    for (int u = 0; u < 4; u++) {
        int f = tid + 256 * u;
        int i = f >> 4;
        int d0 = (f & 15) << 2;
        float4 qv = *(const float4*)&base[(size_t)(qrow0 + i) * QKV_N + hoff + d0];
        qT[(d0 + 0) * PADT + i] = qv.x;
        qT[(d0 + 1) * PADT + i] = qv.y;
        qT[(d0 + 2) * PADT + i] = qv.z;
        qT[(d0 + 3) * PADT + i] = qv.w;
    }

    float o[4][4];
    float m_run[4], l_run[4];
#pragma unroll
    for (int ii = 0; ii < 4; ii++) {
        m_run[ii] = -1e30f; l_run[ii] = 0.f;
#pragma unroll
        for (int cc = 0; cc < 4; cc++) o[ii][cc] = 0.f;
    }

    for (int kb = 0; kb < SEQ / 64; kb++) {
        __syncthreads();   // prev PV reads of kT/vS/pT complete
        const int kr0 = kb * 64;
#pragma unroll
        for (int u = 0; u < 4; u++) {
            int f = tid + 256 * u;
            int j = f >> 4;
            int d0 = (f & 15) << 2;
            const float* rp = &base[(size_t)(kr0 + j) * QKV_N];
            float4 kv = *(const float4*)&rp[DIM + hoff + d0];
            kT[(d0 + 0) * PADT + j] = kv.x;
            kT[(d0 + 1) * PADT + j] = kv.y;
            kT[(d0 + 2) * PADT + j] = kv.z;
            kT[(d0 + 3) * PADT + j] = kv.w;
            float4 vv = *(const float4*)&rp[2 * DIM + hoff + d0];
            *(float4*)&vS[j * 64 + d0] = vv;
        }
        __syncthreads();

        // S = Q K^T (4x4 per thread)
        float ss[4][4];
#pragma unroll
        for (int ii = 0; ii < 4; ii++)
#pragma unroll
            for (int jj = 0; jj < 4; jj++) ss[ii][jj] = 0.f;

#pragma unroll 8
        for (int d = 0; d < 64; d++) {
            float4 qa = *(const float4*)&qT[d * PADT + i0];
            float4 ka = *(const float4*)&kT[d * PADT + c0];
            float aq[4] = {qa.x, qa.y, qa.z, qa.w};
            float ak[4] = {ka.x, ka.y, ka.z, ka.w};
#pragma unroll
            for (int ii = 0; ii < 4; ii++)
#pragma unroll
                for (int jj = 0; jj < 4; jj++)
                    ss[ii][jj] += aq[ii] * ak[jj];
        }

        // online softmax: rows i0..i0+3 live entirely in this 16-lane half-warp
#pragma unroll
        for (int ii = 0; ii < 4; ii++) {
            float mx = fmaxf(fmaxf(ss[ii][0], ss[ii][1]), fmaxf(ss[ii][2], ss[ii][3]));
#pragma unroll
            for (int off = 8; off > 0; off >>= 1)
                mx = fmaxf(mx, __shfl_xor_sync(0xffffffffu, mx, off));
            float mn = fmaxf(m_run[ii], mx);
            float alpha = __expf(m_run[ii] - mn);
            float sum = 0.f;
#pragma unroll
            for (int jj = 0; jj < 4; jj++) {
                float p = __expf(ss[ii][jj] - mn);
                pT[(c0 + jj) * PADT + i0 + ii] = p;   // store transposed [j][i]
                sum += p;
            }
#pragma unroll
            for (int off = 8; off > 0; off >>= 1)
                sum += __shfl_xor_sync(0xffffffffu, sum, off);
            l_run[ii] = l_run[ii] * alpha + sum;
            m_run[ii] = mn;
#pragma unroll
            for (int cc = 0; cc < 4; cc++) o[ii][cc] *= alpha;
        }
        __syncthreads();   // pT fully written

        // O += P V
#pragma unroll 8
        for (int j = 0; j < 64; j++) {
            float4 pa = *(const float4*)&pT[j * PADT + i0];
            float4 va = *(const float4*)&vS[j * 64 + c0];
            float ap[4] = {pa.x, pa.y, pa.z, pa.w};
            float av[4] = {va.x, va.y, va.z, va.w};
#pragma unroll
            for (int ii = 0; ii < 4; ii++)
#pragma unroll
                for (int cc = 0; cc < 4; cc++)
                    o[ii][cc] += ap[ii] * av[cc];
        }
    }

    // normalize and store: out[b][n][h*64 + c]
#pragma unroll
    for (int ii = 0; ii < 4; ii++) {
        float inv = 1.f / l_run[ii];
        float4 w4 = make_float4(o[ii][0] * inv, o[ii][1] * inv,
                                o[ii][2] * inv, o[ii][3] * inv);
        *(float4*)&aout[(size_t)b * SEQ * DIM +
                        (size_t)(qrow0 + i0 + ii) * DIM + hoff + c0] = w4;
    }
}

// ---------------- launch ----------------
extern "C" void kernel_launch(void* const* d_in, const int* in_sizes, int n_in,
                              void* d_out, int out_size)
{
    const float* x      = (const float*)d_in[0];
    const float* qkv_w  = (const float*)d_in[1];
    const float* proj_w = (const float*)d_in[2];
    const float* proj_b = (const float*)d_in[3];
    const float* A1     = (const float*)d_in[4];
    const float* B1     = (const float*)d_in[5];
    const float* A2     = (const float*)d_in[6];
    const float* B2     = (const float*)d_in[7];
    float* out = (float*)d_out;

    float *p_qkv, *p_attn, *p_t1, *p_t2;
    cudaGetSymbolAddress((void**)&p_qkv,  g_qkv);
    cudaGetSymbolAddress((void**)&p_attn, g_attn);
    cudaGetSymbolAddress((void**)&p_t1,   g_t1);
    cudaGetSymbolAddress((void**)&p_t2,   g_t2);

    const int smem_attn = (3 * 64 * PADT + 64 * 64) * (int)sizeof(float); // 68608
    cudaFuncSetAttribute(attn_kernel, cudaFuncAttributeMaxDynamicSharedMemorySize, smem_attn);

    // 1) t1 = 2*(x @ A1^T)
    lora_down_kernel<<<MTOT * 32 / 256, 256>>>(x, A1, p_t1);

    // 2) qkv = x @ qkv_w^T + t1 @ B1^T ; q cols scaled
    sgemm_epi<1><<<dim3(QKV_N / 128, MTOT / 128), 256>>>(
        x, qkv_w, p_qkv, MTOT, QKV_N, DIM, p_t1, B1, nullptr);

    // 3) flash attention
    attn_kernel<<<dim3(SEQ / 64, 16, 2), 256, smem_attn>>>(p_qkv, p_attn);

    // 4) t2 = 2*(attn @ A2^T)
    lora_down_kernel<<<MTOT * 32 / 256, 256>>>(p_attn, A2, p_t2);

    // 5) out = attn @ proj_w^T + proj_b + t2 @ B2^T
    sgemm_epi<2><<<dim3(DIM / 128, MTOT / 128), 256>>>(
        p_attn, proj_w, out, MTOT, DIM, DIM, p_t2, B2, proj_b);
}

// round 2
// speedup vs baseline: 3.1818x; 3.1818x over previous
#include <cuda_runtime.h>
#include <cstdint>

#define DIM    1024
#define QKV_N  3072
#define MTOT   4096          // B*N
#define SEQ    2048
#define RANK   8
#define LSCALE 2.0f
#define QSCALE 0.125f

// -------- scratch --------
__device__ float g_qkv[MTOT * QKV_N];
__device__ float g_attn[MTOT * DIM];
__device__ float g_t1[MTOT * RANK];
__device__ float g_t2[MTOT * RANK];

// -------- tf32 helpers --------
__device__ __forceinline__ unsigned f2tf(float x) {
    unsigned u; asm("cvt.rna.tf32.f32 %0, %1;" : "=r"(u) : "f"(x)); return u;
}
__device__ __forceinline__ void mma8(float* d, const unsigned* a, unsigned b0, unsigned b1) {
    asm("mma.sync.aligned.m16n8k8.row.col.f32.tf32.tf32.f32 "
        "{%0,%1,%2,%3},{%4,%5,%6,%7},{%8,%9},{%0,%1,%2,%3};"
        : "+f"(d[0]), "+f"(d[1]), "+f"(d[2]), "+f"(d[3])
        : "r"(a[0]), "r"(a[1]), "r"(a[2]), "r"(a[3]), "r"(b0), "r"(b1));
}
__device__ __forceinline__ uint4 pack_tf(float4 v) {
    uint4 u; u.x = f2tf(v.x); u.y = f2tf(v.y); u.z = f2tf(v.z); u.w = f2tf(v.w); return u;
}

// ---------------- LoRA down: t = LSCALE * (X @ A^T), one warp per row ----------------
__global__ void lora_down_kernel(const float* __restrict__ x,
                                 const float* __restrict__ A,
                                 float* __restrict__ t)
{
    int warp = (blockIdx.x * blockDim.x + threadIdx.x) >> 5;
    int lane = threadIdx.x & 31;
    if (warp >= MTOT) return;
    const float4* xr = (const float4*)(x + (size_t)warp * DIM);
    float acc[RANK];
#pragma unroll
    for (int r = 0; r < RANK; r++) acc[r] = 0.f;
#pragma unroll
    for (int k = lane; k < DIM / 4; k += 32) {
        float4 xv = xr[k];
#pragma unroll
        for (int r = 0; r < RANK; r++) {
            float4 av = *(const float4*)&A[r * DIM + 4 * k];
            acc[r] += xv.x * av.x + xv.y * av.y + xv.z * av.z + xv.w * av.w;
        }
    }
#pragma unroll
    for (int r = 0; r < RANK; r++) {
#pragma unroll
        for (int off = 16; off > 0; off >>= 1)
            acc[r] += __shfl_xor_sync(0xffffffffu, acc[r], off);
    }
    if (lane == 0) {
#pragma unroll
        for (int r = 0; r < RANK; r++)
            t[warp * RANK + r] = LSCALE * acc[r];
    }
}

// ---------------- TF32 tensor-core GEMM: C = A[M,K] @ W[N,K]^T (+ LoRA epilogue) -------
// 128x128 tile, BK=32, 256 thr = 8 warps (2m x 4n), warp tile 64x32, mma m16n8k8
#define GST 36   // smem row stride (32 + 4 pad): frag-load bank = 4g + t4, conflict-free

template<int EPI>   // 1: qkv (q cols *QSCALE), 2: proj (+bias)
__global__ void __launch_bounds__(256, 2) gemm_tc(
    const float* __restrict__ A, const float* __restrict__ W,
    float* __restrict__ C, int M, int N, int K,
    const float* __restrict__ lt, const float* __restrict__ lB,
    const float* __restrict__ bias)
{
    __shared__ unsigned As[128 * GST];
    __shared__ unsigned Bs[128 * GST];
    const int tid = threadIdx.x, warp = tid >> 5, lane = tid & 31;
    const int g = lane >> 2, t4 = lane & 3;
    const int bm = blockIdx.y * 128, bn = blockIdx.x * 128;
    const int wm = (warp & 1) * 64, wn = (warp >> 1) * 32;

    float acc[4][4][4];
#pragma unroll
    for (int mt = 0; mt < 4; mt++)
#pragma unroll
        for (int nt = 0; nt < 4; nt++)
#pragma unroll
            for (int e = 0; e < 4; e++) acc[mt][nt][e] = 0.f;

    for (int k0 = 0; k0 < K; k0 += 32) {
        uint4 av[4], bv[4];
#pragma unroll
        for (int u = 0; u < 4; u++) {
            int f = tid + 256 * u;
            int r = f >> 3, c4 = (f & 7) << 2;
            av[u] = pack_tf(*(const float4*)&A[(size_t)(bm + r) * K + k0 + c4]);
            bv[u] = pack_tf(*(const float4*)&W[(size_t)(bn + r) * K + k0 + c4]);
        }
        __syncthreads();
#pragma unroll
        for (int u = 0; u < 4; u++) {
            int f = tid + 256 * u;
            int r = f >> 3, c4 = (f & 7) << 2;
            *(uint4*)&As[r * GST + c4] = av[u];
            *(uint4*)&Bs[r * GST + c4] = bv[u];
        }
        __syncthreads();
#pragma unroll
        for (int ks = 0; ks < 4; ks++) {
            const int kk = ks * 8;
            unsigned af[4][4];
#pragma unroll
            for (int mt = 0; mt < 4; mt++) {
                int r0 = (wm + 16 * mt + g) * GST + kk + t4;
                af[mt][0] = As[r0];
                af[mt][1] = As[r0 + 8 * GST];
                af[mt][2] = As[r0 + 4];
                af[mt][3] = As[r0 + 8 * GST + 4];
            }
#pragma unroll
            for (int nt = 0; nt < 4; nt++) {
                int bb = (wn + 8 * nt + g) * GST + kk + t4;
                unsigned b0 = Bs[bb], b1 = Bs[bb + 4];
#pragma unroll
                for (int mt = 0; mt < 4; mt++)
                    mma8(acc[mt][nt], af[mt], b0, b1);
            }
        }
    }

    // epilogue: + lt @ lB^T (+bias) (*QSCALE on q cols)
#pragma unroll
    for (int mt = 0; mt < 4; mt++) {
        const int r0 = bm + wm + 16 * mt + g;
        float lt0[RANK], lt1[RANK];
#pragma unroll
        for (int r = 0; r < RANK; r++) {
            lt0[r] = lt[r0 * RANK + r];
            lt1[r] = lt[(r0 + 8) * RANK + r];
        }
#pragma unroll
        for (int nt = 0; nt < 4; nt++) {
            const int c0 = bn + wn + 8 * nt + 2 * t4;
            float v[4] = {acc[mt][nt][0], acc[mt][nt][1], acc[mt][nt][2], acc[mt][nt][3]};
#pragma unroll
            for (int e = 0; e < 2; e++) {   // two cols c0+e
                const int gc = c0 + e;
                float s0 = 0.f, s1 = 0.f;
#pragma unroll
                for (int r = 0; r < RANK; r++) {
                    float bw = lB[gc * RANK + r];
                    s0 += lt0[r] * bw;
                    s1 += lt1[r] * bw;
                }
                v[e]     += s0;
                v[2 + e] += s1;
                if (EPI == 2) { float bb = bias[gc]; v[e] += bb; v[2 + e] += bb; }
                if (EPI == 1 && gc < DIM) { v[e] *= QSCALE; v[2 + e] *= QSCALE; }
            }
            *(float2*)&C[(size_t)r0 * N + c0]       = make_float2(v[0], v[1]);
            *(float2*)&C[(size_t)(r0 + 8) * N + c0] = make_float2(v[2], v[3]);
        }
    }
}

// ---------------- TF32 tensor-core flash attention ----------------
// q-tile 128 x k-tile 64, 256 thr = 8 warps x 16 rows. Q frags in regs.
#define AST 68   // Ps/Ks stride (64+4)
#define VST 72   // Vs stride (64+8): b-frag bank = 8*t4 + g, conflict-free

__global__ void __launch_bounds__(256, 1) attn_tc(const float* __restrict__ qkv,
                                                  float* __restrict__ aout)
{
    extern __shared__ unsigned smem_u[];
    unsigned* Ps = smem_u;                  // 128*AST (Q staging, then P)
    unsigned* Ks = smem_u + 128 * AST;      // 64*AST
    unsigned* Vs = Ks + 64 * AST;           // 64*VST

    const int tid = threadIdx.x, warp = tid >> 5, lane = tid & 31;
    const int g = lane >> 2, t4 = lane & 3;
    const int qt = blockIdx.x, h = blockIdx.y, b = blockIdx.z;
    const float* base = qkv + (size_t)b * SEQ * QKV_N;
    const int qrow0 = qt * 128, hoff = h * 64, wr = warp * 16;

    // stage Q (tf32) into Ps
#pragma unroll
    for (int u = 0; u < 8; u++) {
        int f = tid + 256 * u;
        int r = f >> 4, d4 = (f & 15) << 2;
        float4 q4 = *(const float4*)&base[(size_t)(qrow0 + r) * QKV_N + hoff + d4];
        *(uint4*)&Ps[r * AST + d4] = pack_tf(q4);
    }
    __syncthreads();

    // Q fragments, register resident for all k-blocks
    unsigned qf[8][4];
    {
        int r0 = (wr + g) * AST, r1 = (wr + 8 + g) * AST;
#pragma unroll
        for (int kk = 0; kk < 8; kk++) {
            int c = kk * 8 + t4;
            qf[kk][0] = Ps[r0 + c];
            qf[kk][1] = Ps[r1 + c];
            qf[kk][2] = Ps[r0 + c + 4];
            qf[kk][3] = Ps[r1 + c + 4];
        }
    }

    float o[8][4];
#pragma unroll
    for (int nt = 0; nt < 8; nt++)
#pragma unroll
        for (int e = 0; e < 4; e++) o[nt][e] = 0.f;
    float mrun[2] = {-1e30f, -1e30f}, lrun[2] = {0.f, 0.f};

    for (int kb = 0; kb < SEQ / 64; kb++) {
        __syncthreads();
        const int kr0 = kb * 64;
#pragma unroll
        for (int u = 0; u < 4; u++) {
            int f = tid + 256 * u;
            int j = f >> 4, d4 = (f & 15) << 2;
            const float* rp = &base[(size_t)(kr0 + j) * QKV_N + hoff + d4];
            float4 k4 = *(const float4*)&rp[DIM];
            float4 v4 = *(const float4*)&rp[2 * DIM];
            *(uint4*)&Ks[j * AST + d4] = pack_tf(k4);
            *(uint4*)&Vs[j * VST + d4] = pack_tf(v4);
        }
        __syncthreads();

        // S = Q K^T : s[nt] rows {wr+g, wr+8+g}, cols {8nt+2t4, +1}
        float s[8][4];
#pragma unroll
        for (int nt = 0; nt < 8; nt++)
#pragma unroll
            for (int e = 0; e < 4; e++) s[nt][e] = 0.f;
#pragma unroll
        for (int nt = 0; nt < 8; nt++) {
            int bb = (8 * nt + g) * AST + t4;
#pragma unroll
            for (int kk = 0; kk < 8; kk++)
                mma8(s[nt], qf[kk], Ks[bb + kk * 8], Ks[bb + kk * 8 + 4]);
        }

        // online softmax per row-half
#pragma unroll
        for (int hh = 0; hh < 2; hh++) {
            float mx = -1e30f;
#pragma unroll
            for (int nt = 0; nt < 8; nt++)
                mx = fmaxf(mx, fmaxf(s[nt][2 * hh], s[nt][2 * hh + 1]));
            mx = fmaxf(mx, __shfl_xor_sync(0xffffffffu, mx, 1));
            mx = fmaxf(mx, __shfl_xor_sync(0xffffffffu, mx, 2));
            float mn = fmaxf(mrun[hh], mx);
            float alpha = __expf(mrun[hh] - mn);
            float sum = 0.f;
            int prow = (wr + g + 8 * hh) * AST;
#pragma unroll
            for (int nt = 0; nt < 8; nt++) {
                float p0 = __expf(s[nt][2 * hh] - mn);
                float p1 = __expf(s[nt][2 * hh + 1] - mn);
                sum += p0 + p1;
                uint2 pp; pp.x = f2tf(p0); pp.y = f2tf(p1);
                *(uint2*)&Ps[prow + 8 * nt + 2 * t4] = pp;
            }
            sum += __shfl_xor_sync(0xffffffffu, sum, 1);
            sum += __shfl_xor_sync(0xffffffffu, sum, 2);
            lrun[hh] = lrun[hh] * alpha + sum;
            mrun[hh] = mn;
#pragma unroll
            for (int nt = 0; nt < 8; nt++) {
                o[nt][2 * hh]     *= alpha;
                o[nt][2 * hh + 1] *= alpha;
            }
        }
        __syncwarp();

        // O += P V  (each warp reads only its own P rows — no block sync needed)
#pragma unroll
        for (int kk = 0; kk < 8; kk++) {
            unsigned pa[4];
            int r0 = (wr + g) * AST + kk * 8 + t4;
            pa[0] = Ps[r0];
            pa[1] = Ps[r0 + 8 * AST];
            pa[2] = Ps[r0 + 4];
            pa[3] = Ps[r0 + 8 * AST + 4];
            int vb0 = (kk * 8 + t4) * VST + g;
            int vb1 = vb0 + 4 * VST;
#pragma unroll
            for (int nt = 0; nt < 8; nt++)
                mma8(o[nt], pa, Vs[vb0 + 8 * nt], Vs[vb1 + 8 * nt]);
        }
    }

    // normalize + store
#pragma unroll
    for (int hh = 0; hh < 2; hh++) {
        float inv = 1.f / lrun[hh];
        int row = qrow0 + wr + g + 8 * hh;
        float* op = &aout[((size_t)b * SEQ + row) * DIM + hoff + 2 * t4];
#pragma unroll
        for (int nt = 0; nt < 8; nt++)
            *(float2*)&op[8 * nt] = make_float2(o[nt][2 * hh] * inv,
                                                o[nt][2 * hh + 1] * inv);
    }
}

// ---------------- launch ----------------
extern "C" void kernel_launch(void* const* d_in, const int* in_sizes, int n_in,
                              void* d_out, int out_size)
{
    const float* x      = (const float*)d_in[0];
    const float* qkv_w  = (const float*)d_in[1];
    const float* proj_w = (const float*)d_in[2];
    const float* proj_b = (const float*)d_in[3];
    const float* A1     = (const float*)d_in[4];
    const float* B1     = (const float*)d_in[5];
    const float* A2     = (const float*)d_in[6];
    const float* B2     = (const float*)d_in[7];
    float* out = (float*)d_out;

    float *p_qkv, *p_attn, *p_t1, *p_t2;
    cudaGetSymbolAddress((void**)&p_qkv,  g_qkv);
    cudaGetSymbolAddress((void**)&p_attn, g_attn);
    cudaGetSymbolAddress((void**)&p_t1,   g_t1);
    cudaGetSymbolAddress((void**)&p_t2,   g_t2);

    const int smem_attn = (128 * AST + 64 * AST + 64 * VST) * (int)sizeof(unsigned);
    cudaFuncSetAttribute(attn_tc, cudaFuncAttributeMaxDynamicSharedMemorySize, smem_attn);

    // 1) t1 = 2*(x @ A1^T)
    lora_down_kernel<<<MTOT * 32 / 256, 256>>>(x, A1, p_t1);

    // 2) qkv = x @ qkv_w^T + t1 @ B1^T ; q cols scaled
    gemm_tc<1><<<dim3(QKV_N / 128, MTOT / 128), 256>>>(
        x, qkv_w, p_qkv, MTOT, QKV_N, DIM, p_t1, B1, nullptr);

    // 3) flash attention (tf32 tensor cores)
    attn_tc<<<dim3(SEQ / 128, 16, 2), 256, smem_attn>>>(p_qkv, p_attn);

    // 4) t2 = 2*(attn @ A2^T)
    lora_down_kernel<<<MTOT * 32 / 256, 256>>>(p_attn, A2, p_t2);

    // 5) out = attn @ proj_w^T + proj_b + t2 @ B2^T
    gemm_tc<2><<<dim3(DIM / 128, MTOT / 128), 256>>>(
        p_attn, proj_w, out, MTOT, DIM, DIM, p_t2, B2, proj_b);
}